// round 11
// baseline (speedup 1.0000x reference)
#include <cuda_runtime.h>
#include <cuda_bf16.h>

// ============================================================================
// Single main kernel:
//   blocks [0, nTiles*NSPLIT): point work. tile = bid % nTiles, split = bid / nTiles.
//     Each block: 64 threads, 512 points (8/thread as 4 packed f32x2 pairs)
//     x 64 nodes (N/NSPLIT). Partials to scratch; LAST split-block per tile
//     (atomic counter) combines all NSPLIT partials in FIXED order -> out.
//   block nTiles*NSPLIT: edge regularizer.
//
// smem per node: 16 replicated float2 slots (128 B):
//   0:r00 1:r01 2:r02 3:u0  4:r10 5:r11 6:r12 7:u1
//   8:r20 9:r21 10:r22 11:u2 12:kx 13:ky 14:kz 15:kc
// u  = t + c - R*c           (contribution = w * (R*p + u))
// k  = 2*SS2*c, kc = -SS2*|c|^2,  SS2 = log2(e)/(2*sigma^2)
// w  = ex2( k.p + kc - SS2*|p|^2 )
// ============================================================================

#define BLOCK_THREADS 64
#define PTS_PER_THREAD 8
#define NPAIR 4
#define PTS_PER_BLOCK (BLOCK_THREADS * PTS_PER_THREAD)   // 512
#define NSPLIT 8
#define MAXP 65536
#define MAXTILES (MAXP / PTS_PER_BLOCK + 1)

__device__ float4 g_part[NSPLIT * MAXP];        // (ax, ay, az, S) partials
__device__ unsigned int g_tilecount[MAXTILES];  // monotone counters (mod NSPLIT)

typedef unsigned long long ull;

// ---- packed f32x2 helpers (sm_103a) ----------------------------------------
__device__ __forceinline__ ull pk2(float a, float b) {
    ull r;
    asm("mov.b64 %0, {%1, %2};" : "=l"(r) : "f"(a), "f"(b));
    return r;
}
__device__ __forceinline__ void upk2(ull v, float& a, float& b) {
    asm("mov.b64 {%0, %1}, %2;" : "=f"(a), "=f"(b) : "l"(v));
}
__device__ __forceinline__ ull add2(ull a, ull b) {
    ull r;
    asm("add.rn.f32x2 %0, %1, %2;" : "=l"(r) : "l"(a), "l"(b));
    return r;
}
__device__ __forceinline__ ull fma2(ull a, ull b, ull c) {
    ull r;
    asm("fma.rn.f32x2 %0, %1, %2, %3;" : "=l"(r) : "l"(a), "l"(b), "l"(c));
    return r;
}
__device__ __forceinline__ float ex2f(float x) {
    float r;
    asm("ex2.approx.f32 %0, %1;" : "=f"(r) : "f"(x));
    return r;
}

// ---- Rodrigues --------------------------------------------------------------
__device__ __forceinline__ void rodrigues(float x, float y, float z, float R[9]) {
    float th2 = x * x + y * y + z * z + 1e-12f;
    float th = sqrtf(th2);
    float s, co;
    sincosf(th, &s, &co);
    float a = s / th;
    float b = (1.0f - co) / th2;
    float xx = x * x, yy = y * y, zz = z * z;
    float xy = x * y, xz = x * z, yz = y * z;
    R[0] = 1.0f - b * (yy + zz);
    R[1] = -a * z + b * xy;
    R[2] =  a * y + b * xz;
    R[3] =  a * z + b * xy;
    R[4] = 1.0f - b * (xx + zz);
    R[5] = -a * x + b * yz;
    R[6] = -a * y + b * xz;
    R[7] =  a * x + b * yz;
    R[8] = 1.0f - b * (xx + yy);
}

// SS2 = (1/(2*sigma^2)) * log2(e) = 0.02 * 1.44269504
#define SS2 0.0288539008f

__global__ void __launch_bounds__(BLOCK_THREADS)
main_kernel(const float* __restrict__ pts,
            const float* __restrict__ cp,
            const float* __restrict__ rv,
            const float* __restrict__ t,
            const int* __restrict__ edges,
            float* __restrict__ out,
            int N, int P, int E, int nTiles, int chunk) {
    extern __shared__ float2 sf[];  // 16 replicated float2 per local node

    // ------------------------------------------------------------------
    // Edge block (last block)
    // ------------------------------------------------------------------
    if (blockIdx.x == (unsigned)(nTiles * NSPLIT)) {
        __shared__ float red[BLOCK_THREADS];
        float acc = 0.0f;
        for (int m = threadIdx.x; m < E; m += BLOCK_THREADS) {
            int i = edges[2 * m + 0];
            int j = edges[2 * m + 1];
            i = min(max(i, 0), N - 1);
            j = min(max(j, 0), N - 1);

            float R[9];
            rodrigues(rv[3 * i + 0], rv[3 * i + 1], rv[3 * i + 2], R);

            float cix = cp[3 * i + 0], ciy = cp[3 * i + 1], ciz = cp[3 * i + 2];
            float cjx = cp[3 * j + 0], cjy = cp[3 * j + 1], cjz = cp[3 * j + 2];
            float tix = t[3 * i + 0],  tiy = t[3 * i + 1],  tiz = t[3 * i + 2];
            float tjx = t[3 * j + 0],  tjy = t[3 * j + 1],  tjz = t[3 * j + 2];

            float dx = cjx - cix, dy = cjy - ciy, dz = cjz - ciz;

            float r0 = fmaf(R[0], dx, fmaf(R[1], dy, R[2] * dz)) + cix + tix - cjx - tjx;
            float r1 = fmaf(R[3], dx, fmaf(R[4], dy, R[5] * dz)) + ciy + tiy - cjy - tjy;
            float r2 = fmaf(R[6], dx, fmaf(R[7], dy, R[8] * dz)) + ciz + tiz - cjz - tjz;

            acc += r0 * r0 + r1 * r1 + r2 * r2;
        }
        red[threadIdx.x] = acc;
        __syncthreads();
        for (int s = BLOCK_THREADS / 2; s > 0; s >>= 1) {
            if (threadIdx.x < (unsigned)s) red[threadIdx.x] += red[threadIdx.x + s];
            __syncthreads();
        }
        if (threadIdx.x == 0) out[3 * P] = red[0];
        return;
    }

    int split = blockIdx.x / nTiles;
    int tile  = blockIdx.x % nTiles;
    int n0 = split * chunk;
    int nNodes = min(chunk, N - n0);
    if (nNodes < 0) nNodes = 0;

    // ------------------------------------------------------------------
    // Stage this split's node constants
    // ------------------------------------------------------------------
    for (int ln = threadIdx.x; ln < nNodes; ln += BLOCK_THREADS) {
        int n = n0 + ln;
        float R[9];
        rodrigues(rv[3 * n + 0], rv[3 * n + 1], rv[3 * n + 2], R);
        float cx = cp[3 * n + 0], cy = cp[3 * n + 1], cz = cp[3 * n + 2];
        float tx = t[3 * n + 0],  ty = t[3 * n + 1],  tz = t[3 * n + 2];
        float u0 = tx + cx - (R[0] * cx + R[1] * cy + R[2] * cz);
        float u1 = ty + cy - (R[3] * cx + R[4] * cy + R[5] * cz);
        float u2 = tz + cz - (R[6] * cx + R[7] * cy + R[8] * cz);
        float kx = 2.0f * SS2 * cx;
        float ky = 2.0f * SS2 * cy;
        float kz = 2.0f * SS2 * cz;
        float kc = -SS2 * (cx * cx + cy * cy + cz * cz);

        float2* s = sf + 16 * ln;
        s[0]  = make_float2(R[0], R[0]);
        s[1]  = make_float2(R[1], R[1]);
        s[2]  = make_float2(R[2], R[2]);
        s[3]  = make_float2(u0, u0);
        s[4]  = make_float2(R[3], R[3]);
        s[5]  = make_float2(R[4], R[4]);
        s[6]  = make_float2(R[5], R[5]);
        s[7]  = make_float2(u1, u1);
        s[8]  = make_float2(R[6], R[6]);
        s[9]  = make_float2(R[7], R[7]);
        s[10] = make_float2(R[8], R[8]);
        s[11] = make_float2(u2, u2);
        s[12] = make_float2(kx, kx);
        s[13] = make_float2(ky, ky);
        s[14] = make_float2(kz, kz);
        s[15] = make_float2(kc, kc);
    }
    __syncthreads();

    // ------------------------------------------------------------------
    // 8 points per thread: 4 independent packed pairs
    // point index for pair k, lane lo/hi: base + tid + (2k+{0,1})*64
    // ------------------------------------------------------------------
    int base = tile * PTS_PER_BLOCK;

    ull px[NPAIR], py[NPAIR], pz[NPAIR];
    float q2lo[NPAIR], q2hi[NPAIR];

#pragma unroll
    for (int k = 0; k < NPAIR; ++k) {
        int pL = base + threadIdx.x + (2 * k + 0) * BLOCK_THREADS;
        int pH = base + threadIdx.x + (2 * k + 1) * BLOCK_THREADS;
        int lL = pL < P ? pL : 0;
        int lH = pH < P ? pH : 0;
        float xa = pts[3 * lL + 0], ya = pts[3 * lL + 1], za = pts[3 * lL + 2];
        float xb = pts[3 * lH + 0], yb = pts[3 * lH + 1], zb = pts[3 * lH + 2];
        px[k] = pk2(xa, xb);
        py[k] = pk2(ya, yb);
        pz[k] = pk2(za, zb);
        q2lo[k] = SS2 * (xa * xa + ya * ya + za * za);
        q2hi[k] = SS2 * (xb * xb + yb * yb + zb * zb);
    }

    ull ax[NPAIR], ay[NPAIR], az[NPAIR], Sw[NPAIR];
#pragma unroll
    for (int k = 0; k < NPAIR; ++k) {
        ax[k] = 0ull; ay[k] = 0ull; az[k] = 0ull; Sw[k] = 0ull;
    }

    const ulonglong2* sm = (const ulonglong2*)sf;

#pragma unroll 2
    for (int n = 0; n < nNodes; ++n) {
        ulonglong2 a0 = sm[8 * n + 0];
        ulonglong2 a1 = sm[8 * n + 1];
        ulonglong2 a2 = sm[8 * n + 2];
        ulonglong2 a3 = sm[8 * n + 3];
        ulonglong2 a4 = sm[8 * n + 4];
        ulonglong2 a5 = sm[8 * n + 5];
        ulonglong2 a6 = sm[8 * n + 6];  // (kx, ky)
        ulonglong2 a7 = sm[8 * n + 7];  // (kz, kc)

#pragma unroll
        for (int k = 0; k < NPAIR; ++k) {
            ull dot = fma2(a6.x, px[k], fma2(a6.y, py[k], fma2(a7.x, pz[k], a7.y)));
            float d0, d1;
            upk2(dot, d0, d1);
            float w0 = ex2f(d0 - q2lo[k]);
            float w1 = ex2f(d1 - q2hi[k]);
            ull ww = pk2(w0, w1);

            ull y0 = fma2(a0.x, px[k], fma2(a0.y, py[k], fma2(a1.x, pz[k], a1.y)));
            ull y1 = fma2(a2.x, px[k], fma2(a2.y, py[k], fma2(a3.x, pz[k], a3.y)));
            ull y2 = fma2(a4.x, px[k], fma2(a4.y, py[k], fma2(a5.x, pz[k], a5.y)));

            ax[k] = fma2(ww, y0, ax[k]);
            ay[k] = fma2(ww, y1, ay[k]);
            az[k] = fma2(ww, y2, az[k]);
            Sw[k] = add2(Sw[k], ww);
        }
    }

    float4* gp = g_part + (size_t)split * P;
#pragma unroll
    for (int k = 0; k < NPAIR; ++k) {
        float xa, xb, ya, yb, za, zb, sa, sb;
        upk2(ax[k], xa, xb);
        upk2(ay[k], ya, yb);
        upk2(az[k], za, zb);
        upk2(Sw[k], sa, sb);
        int pL = base + threadIdx.x + (2 * k + 0) * BLOCK_THREADS;
        int pH = base + threadIdx.x + (2 * k + 1) * BLOCK_THREADS;
        if (pL < P) gp[pL] = make_float4(xa, ya, za, sa);
        if (pH < P) gp[pH] = make_float4(xb, yb, zb, sb);
    }

    // ------------------------------------------------------------------
    // Last split-block of this tile combines (fixed split order -> deterministic)
    // ------------------------------------------------------------------
    __threadfence();
    __shared__ unsigned int sOld;
    if (threadIdx.x == 0)
        sOld = atomicAdd(&g_tilecount[tile], 1u);
    __syncthreads();
    if ((sOld % NSPLIT) != (NSPLIT - 1)) return;

#pragma unroll
    for (int q = 0; q < PTS_PER_THREAD; ++q) {
        int p = base + q * BLOCK_THREADS + threadIdx.x;
        if (p >= P) break;
        float axv = 0.0f, ayv = 0.0f, azv = 0.0f, Sv = 0.0f;
#pragma unroll
        for (int s = 0; s < NSPLIT; ++s) {
            float4 v = __ldcg(&g_part[(size_t)s * P + p]);  // L2-coherent read
            axv += v.x; ayv += v.y; azv += v.z; Sv += v.w;
        }
        float inv = 1.0f / (Sv + 1e-5f);
        out[3 * p + 0] = axv * inv;
        out[3 * p + 1] = ayv * inv;
        out[3 * p + 2] = azv * inv;
    }
}

// ---------------------------------------------------------------------------
extern "C" void kernel_launch(void* const* d_in, const int* in_sizes, int n_in,
                              void* d_out, int out_size) {
    const float* points  = (const float*)d_in[0];
    const float* cp      = (const float*)d_in[1];
    const float* rot_vec = (const float*)d_in[2];
    const float* t       = (const float*)d_in[3];
    const int*   edges   = (const int*)d_in[4];

    float* out = (float*)d_out;

    int P = in_sizes[0] / 3;
    if (P > MAXP) P = MAXP;  // defensive (scratch bound)
    int N = in_sizes[1] / 3;
    int E = in_sizes[4] / 2;

    int nTiles = (P + PTS_PER_BLOCK - 1) / PTS_PER_BLOCK;
    int chunk = (N + NSPLIT - 1) / NSPLIT;
    size_t smem = (size_t)chunk * 16 * sizeof(float2);  // 128 B per node

    main_kernel<<<nTiles * NSPLIT + 1, BLOCK_THREADS, smem>>>(
        points, cp, rot_vec, t, edges, out, N, P, E, nTiles, chunk);
}

// round 12
// speedup vs baseline: 1.3796x; 1.3796x over previous
#include <cuda_runtime.h>
#include <cuda_bf16.h>

// ============================================================================
// Single main kernel (R7 structure):
//   blocks [0, nTiles*NSPLIT): point work. tile = bid % nTiles, split = bid / nTiles.
//     Each block: 128 threads, 512 points (4/thread, 2 packed f32x2 pairs)
//     x 64 nodes (N/NSPLIT). Partials to scratch; LAST split-block per tile
//     (atomic counter) combines all NSPLIT partials in FIXED order -> out.
//   block nTiles*NSPLIT: edge regularizer.
//
// Weight trick: w' = ex2(k.p + kc) = w * 2^{q2}  (per-point scale cancels in
// ax/S). Epilogue uses eps = 1e-5 * 2^{q2} so S + 1e-5 semantics are exact.
//
// smem per node: 16 replicated float2 slots (128 B):
//   0:r00 1:r01 2:r02 3:u0  4:r10 5:r11 6:r12 7:u1
//   8:r20 9:r21 10:r22 11:u2 12:kx 13:ky 14:kz 15:kc
// u = t + c - R*c  (contribution = w * (R*p + u))
// k = 2*SS2*c, kc = -SS2*|c|^2,  SS2 = log2(e)/(2*sigma^2)
// ============================================================================

#define BLOCK_THREADS 128
#define PTS_PER_BLOCK 512      // 4 points per thread
#define NSPLIT 8
#define MAXP 65536
#define MAXTILES (MAXP / PTS_PER_BLOCK + 1)

__device__ float4 g_part[NSPLIT * MAXP];        // (ax, ay, az, S) partials
__device__ unsigned int g_tilecount[MAXTILES];  // monotone counters (mod NSPLIT)

typedef unsigned long long ull;

// ---- packed f32x2 helpers (sm_103a) ----------------------------------------
__device__ __forceinline__ ull pk2(float a, float b) {
    ull r;
    asm("mov.b64 %0, {%1, %2};" : "=l"(r) : "f"(a), "f"(b));
    return r;
}
__device__ __forceinline__ void upk2(ull v, float& a, float& b) {
    asm("mov.b64 {%0, %1}, %2;" : "=f"(a), "=f"(b) : "l"(v));
}
__device__ __forceinline__ ull add2(ull a, ull b) {
    ull r;
    asm("add.rn.f32x2 %0, %1, %2;" : "=l"(r) : "l"(a), "l"(b));
    return r;
}
__device__ __forceinline__ ull fma2(ull a, ull b, ull c) {
    ull r;
    asm("fma.rn.f32x2 %0, %1, %2, %3;" : "=l"(r) : "l"(a), "l"(b), "l"(c));
    return r;
}
__device__ __forceinline__ float ex2f(float x) {
    float r;
    asm("ex2.approx.f32 %0, %1;" : "=f"(r) : "f"(x));
    return r;
}

// ---- Rodrigues --------------------------------------------------------------
__device__ __forceinline__ void rodrigues(float x, float y, float z, float R[9]) {
    float th2 = x * x + y * y + z * z + 1e-12f;
    float th = sqrtf(th2);
    float s, co;
    sincosf(th, &s, &co);
    float a = s / th;
    float b = (1.0f - co) / th2;
    float xx = x * x, yy = y * y, zz = z * z;
    float xy = x * y, xz = x * z, yz = y * z;
    R[0] = 1.0f - b * (yy + zz);
    R[1] = -a * z + b * xy;
    R[2] =  a * y + b * xz;
    R[3] =  a * z + b * xy;
    R[4] = 1.0f - b * (xx + zz);
    R[5] = -a * x + b * yz;
    R[6] = -a * y + b * xz;
    R[7] =  a * x + b * yz;
    R[8] = 1.0f - b * (xx + yy);
}

// SS2 = (1/(2*sigma^2)) * log2(e) = 0.02 * 1.44269504
#define SS2 0.0288539008f

__global__ void __launch_bounds__(BLOCK_THREADS)
main_kernel(const float* __restrict__ pts,
            const float* __restrict__ cp,
            const float* __restrict__ rv,
            const float* __restrict__ t,
            const int* __restrict__ edges,
            float* __restrict__ out,
            int N, int P, int E, int nTiles, int chunk) {
    extern __shared__ float2 sf[];  // 16 replicated float2 per local node

    // ------------------------------------------------------------------
    // Edge block (last block)
    // ------------------------------------------------------------------
    if (blockIdx.x == (unsigned)(nTiles * NSPLIT)) {
        __shared__ float red[BLOCK_THREADS];
        float acc = 0.0f;
        for (int m = threadIdx.x; m < E; m += BLOCK_THREADS) {
            int i = edges[2 * m + 0];
            int j = edges[2 * m + 1];
            i = min(max(i, 0), N - 1);
            j = min(max(j, 0), N - 1);

            float R[9];
            rodrigues(rv[3 * i + 0], rv[3 * i + 1], rv[3 * i + 2], R);

            float cix = cp[3 * i + 0], ciy = cp[3 * i + 1], ciz = cp[3 * i + 2];
            float cjx = cp[3 * j + 0], cjy = cp[3 * j + 1], cjz = cp[3 * j + 2];
            float tix = t[3 * i + 0],  tiy = t[3 * i + 1],  tiz = t[3 * i + 2];
            float tjx = t[3 * j + 0],  tjy = t[3 * j + 1],  tjz = t[3 * j + 2];

            float dx = cjx - cix, dy = cjy - ciy, dz = cjz - ciz;

            float r0 = fmaf(R[0], dx, fmaf(R[1], dy, R[2] * dz)) + cix + tix - cjx - tjx;
            float r1 = fmaf(R[3], dx, fmaf(R[4], dy, R[5] * dz)) + ciy + tiy - cjy - tjy;
            float r2 = fmaf(R[6], dx, fmaf(R[7], dy, R[8] * dz)) + ciz + tiz - cjz - tjz;

            acc += r0 * r0 + r1 * r1 + r2 * r2;
        }
        red[threadIdx.x] = acc;
        __syncthreads();
        for (int s = BLOCK_THREADS / 2; s > 0; s >>= 1) {
            if (threadIdx.x < (unsigned)s) red[threadIdx.x] += red[threadIdx.x + s];
            __syncthreads();
        }
        if (threadIdx.x == 0) out[3 * P] = red[0];
        return;
    }

    int split = blockIdx.x / nTiles;
    int tile  = blockIdx.x % nTiles;
    int n0 = split * chunk;
    int nNodes = min(chunk, N - n0);
    if (nNodes < 0) nNodes = 0;

    // ------------------------------------------------------------------
    // Stage this split's node constants
    // ------------------------------------------------------------------
    for (int ln = threadIdx.x; ln < nNodes; ln += BLOCK_THREADS) {
        int n = n0 + ln;
        float R[9];
        rodrigues(rv[3 * n + 0], rv[3 * n + 1], rv[3 * n + 2], R);
        float cx = cp[3 * n + 0], cy = cp[3 * n + 1], cz = cp[3 * n + 2];
        float tx = t[3 * n + 0],  ty = t[3 * n + 1],  tz = t[3 * n + 2];
        float u0 = tx + cx - (R[0] * cx + R[1] * cy + R[2] * cz);
        float u1 = ty + cy - (R[3] * cx + R[4] * cy + R[5] * cz);
        float u2 = tz + cz - (R[6] * cx + R[7] * cy + R[8] * cz);
        float kx = 2.0f * SS2 * cx;
        float ky = 2.0f * SS2 * cy;
        float kz = 2.0f * SS2 * cz;
        float kc = -SS2 * (cx * cx + cy * cy + cz * cz);

        float2* s = sf + 16 * ln;
        s[0]  = make_float2(R[0], R[0]);
        s[1]  = make_float2(R[1], R[1]);
        s[2]  = make_float2(R[2], R[2]);
        s[3]  = make_float2(u0, u0);
        s[4]  = make_float2(R[3], R[3]);
        s[5]  = make_float2(R[4], R[4]);
        s[6]  = make_float2(R[5], R[5]);
        s[7]  = make_float2(u1, u1);
        s[8]  = make_float2(R[6], R[6]);
        s[9]  = make_float2(R[7], R[7]);
        s[10] = make_float2(R[8], R[8]);
        s[11] = make_float2(u2, u2);
        s[12] = make_float2(kx, kx);
        s[13] = make_float2(ky, ky);
        s[14] = make_float2(kz, kz);
        s[15] = make_float2(kc, kc);
    }
    __syncthreads();

    // ------------------------------------------------------------------
    // 4 points per thread (2 packed pairs); weights scaled by 2^{q2}
    // ------------------------------------------------------------------
    int base = tile * PTS_PER_BLOCK;
    int pA = base + threadIdx.x;
    int pB = pA + BLOCK_THREADS;
    int pC = pB + BLOCK_THREADS;
    int pD = pC + BLOCK_THREADS;
    bool vA = pA < P, vB = pB < P, vC = pC < P, vD = pD < P;
    int lA = vA ? pA : 0, lB = vB ? pB : 0, lC = vC ? pC : 0, lD = vD ? pD : 0;

    float pxA = pts[3 * lA + 0], pyA = pts[3 * lA + 1], pzA = pts[3 * lA + 2];
    float pxB = pts[3 * lB + 0], pyB = pts[3 * lB + 1], pzB = pts[3 * lB + 2];
    float pxC = pts[3 * lC + 0], pyC = pts[3 * lC + 1], pzC = pts[3 * lC + 2];
    float pxD = pts[3 * lD + 0], pyD = pts[3 * lD + 1], pzD = pts[3 * lD + 2];

    ull px1 = pk2(pxA, pxB), py1 = pk2(pyA, pyB), pz1 = pk2(pzA, pzB);
    ull px2 = pk2(pxC, pxD), py2 = pk2(pyC, pyD), pz2 = pk2(pzC, pzD);

    ull ax1 = 0ull, ay1 = 0ull, az1 = 0ull, S1 = 0ull;
    ull ax2 = 0ull, ay2 = 0ull, az2 = 0ull, S2 = 0ull;

    const ulonglong2* sm = (const ulonglong2*)sf;

#pragma unroll 2
    for (int n = 0; n < nNodes; ++n) {
        ulonglong2 a0 = sm[8 * n + 0];
        ulonglong2 a1 = sm[8 * n + 1];
        ulonglong2 a2 = sm[8 * n + 2];
        ulonglong2 a3 = sm[8 * n + 3];
        ulonglong2 a4 = sm[8 * n + 4];
        ulonglong2 a5 = sm[8 * n + 5];
        ulonglong2 a6 = sm[8 * n + 6];  // (kx, ky)
        ulonglong2 a7 = sm[8 * n + 7];  // (kz, kc)

        {
            ull dot = fma2(a6.x, px1, fma2(a6.y, py1, fma2(a7.x, pz1, a7.y)));
            float d0, d1;
            upk2(dot, d0, d1);
            float w0 = ex2f(d0);      // scaled weight w' = w * 2^{q2}
            float w1 = ex2f(d1);
            ull ww = pk2(w0, w1);

            ull y0 = fma2(a0.x, px1, fma2(a0.y, py1, fma2(a1.x, pz1, a1.y)));
            ull y1 = fma2(a2.x, px1, fma2(a2.y, py1, fma2(a3.x, pz1, a3.y)));
            ull y2 = fma2(a4.x, px1, fma2(a4.y, py1, fma2(a5.x, pz1, a5.y)));

            ax1 = fma2(ww, y0, ax1);
            ay1 = fma2(ww, y1, ay1);
            az1 = fma2(ww, y2, az1);
            S1 = add2(S1, ww);
        }
        {
            ull dot = fma2(a6.x, px2, fma2(a6.y, py2, fma2(a7.x, pz2, a7.y)));
            float d0, d1;
            upk2(dot, d0, d1);
            float w0 = ex2f(d0);
            float w1 = ex2f(d1);
            ull ww = pk2(w0, w1);

            ull y0 = fma2(a0.x, px2, fma2(a0.y, py2, fma2(a1.x, pz2, a1.y)));
            ull y1 = fma2(a2.x, px2, fma2(a2.y, py2, fma2(a3.x, pz2, a3.y)));
            ull y2 = fma2(a4.x, px2, fma2(a4.y, py2, fma2(a5.x, pz2, a5.y)));

            ax2 = fma2(ww, y0, ax2);
            ay2 = fma2(ww, y1, ay2);
            az2 = fma2(ww, y2, az2);
            S2 = add2(S2, ww);
        }
    }

    float axA, axB, ayA, ayB, azA, azB, SA, SB;
    upk2(ax1, axA, axB);
    upk2(ay1, ayA, ayB);
    upk2(az1, azA, azB);
    upk2(S1, SA, SB);
    float axC, axD, ayC, ayD, azC, azD, SC, SD;
    upk2(ax2, axC, axD);
    upk2(ay2, ayC, ayD);
    upk2(az2, azC, azD);
    upk2(S2, SC, SD);

    float4* gp = g_part + (size_t)split * P;
    if (vA) gp[pA] = make_float4(axA, ayA, azA, SA);
    if (vB) gp[pB] = make_float4(axB, ayB, azB, SB);
    if (vC) gp[pC] = make_float4(axC, ayC, azC, SC);
    if (vD) gp[pD] = make_float4(axD, ayD, azD, SD);

    // ------------------------------------------------------------------
    // Last split-block of this tile combines (fixed split order -> deterministic)
    // out = ax' / (S' + 1e-5 * 2^{q2})   [exact: divide num/den by 2^{q2}]
    // ------------------------------------------------------------------
    __threadfence();
    __shared__ unsigned int sOld;
    if (threadIdx.x == 0)
        sOld = atomicAdd(&g_tilecount[tile], 1u);
    __syncthreads();
    if ((sOld % NSPLIT) != (NSPLIT - 1)) return;

#pragma unroll
    for (int q = 0; q < 4; ++q) {
        int p = base + q * BLOCK_THREADS + threadIdx.x;
        if (p >= P) break;
        float axv = 0.0f, ayv = 0.0f, azv = 0.0f, Sv = 0.0f;
#pragma unroll
        for (int s = 0; s < NSPLIT; ++s) {
            float4 v = __ldcg(&g_part[(size_t)s * P + p]);  // L2-coherent read
            axv += v.x; ayv += v.y; azv += v.z; Sv += v.w;
        }
        float ppx = pts[3 * p + 0], ppy = pts[3 * p + 1], ppz = pts[3 * p + 2];
        float q2 = SS2 * (ppx * ppx + ppy * ppy + ppz * ppz);
        float eps = 1e-5f * ex2f(q2);
        float inv = 1.0f / (Sv + eps);
        out[3 * p + 0] = axv * inv;
        out[3 * p + 1] = ayv * inv;
        out[3 * p + 2] = azv * inv;
    }
}

// ---------------------------------------------------------------------------
extern "C" void kernel_launch(void* const* d_in, const int* in_sizes, int n_in,
                              void* d_out, int out_size) {
    const float* points  = (const float*)d_in[0];
    const float* cp      = (const float*)d_in[1];
    const float* rot_vec = (const float*)d_in[2];
    const float* t       = (const float*)d_in[3];
    const int*   edges   = (const int*)d_in[4];

    float* out = (float*)d_out;

    int P = in_sizes[0] / 3;
    if (P > MAXP) P = MAXP;  // defensive (scratch bound)
    int N = in_sizes[1] / 3;
    int E = in_sizes[4] / 2;

    int nTiles = (P + PTS_PER_BLOCK - 1) / PTS_PER_BLOCK;
    int chunk = (N + NSPLIT - 1) / NSPLIT;
    size_t smem = (size_t)chunk * 16 * sizeof(float2);  // 128 B per node

    main_kernel<<<nTiles * NSPLIT + 1, BLOCK_THREADS, smem>>>(
        points, cp, rot_vec, t, edges, out, N, P, E, nTiles, chunk);
}